// round 3
// baseline (speedup 1.0000x reference)
#include <cuda_runtime.h>
#include <cuda_bf16.h>

// Problem constants
#define Bn   16
#define CIN  64
#define COUT 64
#define Hdim 128
#define Wdim 128
#define HE   8

// Conv tiling: 32x32 pixel tile, 16 co per block, 4 px x 16 co per thread
#define TW 32
#define TH 32
#define CHUNK 16                    // ci per smem stage (4 stages)
#define XPITCH 35                   // 34 used cols, odd pitch -> conflict-free
#define XS_CH (CHUNK * 34 * XPITCH) // 19040 floats
#define WS_CH (CHUNK * 9 * 16)      // 2304 floats
#define SMEM_BYTES ((XS_CH + WS_CH) * 4)  // 85376 B -> 2 CTAs/SM

// Scratch (static device globals; no runtime allocation)
__device__ float g_k3[Bn * 32 * 9];                    // [b][c][tap]
__device__ float g_w[Bn * 4 * 64 * 9 * 16];            // [b][cog][ci][tap][co16]

__device__ __forceinline__ float lrelu(float v) { return v > 0.f ? v : 0.01f * v; }

__device__ __forceinline__ void fma2(unsigned long long& acc, unsigned long long a,
                                     unsigned long long b) {
    asm("fma.rn.f32x2 %0, %1, %2, %0;" : "+l"(acc) : "l"(a), "l"(b));
}
__device__ __forceinline__ unsigned long long pack2(float lo, float hi) {
    unsigned long long r;
    asm("mov.b64 %0, {%1, %2};" : "=l"(r) : "f"(lo), "f"(hi));
    return r;
}
__device__ __forceinline__ void unpack2(unsigned long long v, float& lo, float& hi) {
    asm("mov.b64 {%0, %1}, %2;" : "=f"(lo), "=f"(hi) : "l"(v));
}

// ---------------------------------------------------------------------------
// Kernel A: hypernet stages 1-3 -> g_k3[b][c(32)][tap(9)].  One block per b.
// ---------------------------------------------------------------------------
__global__ void knet_kernel(const float* __restrict__ h,
                            const float* __restrict__ fc_w,
                            const float* __restrict__ fc_b,
                            const float* __restrict__ w1, const float* __restrict__ b1,
                            const float* __restrict__ w2, const float* __restrict__ b2) {
    int b = blockIdx.x;
    __shared__ float k1[144];
    __shared__ float k2[288];
    int tid = threadIdx.x;

    if (tid < 144) {
        float s = fc_b[tid];
#pragma unroll
        for (int q = 0; q < HE; q++) s += h[b * HE + q] * fc_w[tid * HE + q];
        k1[tid] = lrelu(s);
    }
    __syncthreads();

    if (tid < 288) {
        int o = tid / 9, t = tid % 9;
        float s = b1[o];
#pragma unroll
        for (int c = 0; c < 16; c++) s += w1[o * 16 + c] * k1[c * 9 + t];
        k2[tid] = lrelu(s);
    }
    __syncthreads();

    if (tid < 288) {
        int o = tid / 9, t = tid % 9;
        float s = b2[o];
#pragma unroll
        for (int c = 0; c < 32; c++) s += w2[o * 32 + c] * k2[c * 9 + t];
        g_k3[b * 288 + tid] = lrelu(s);
    }
}

// ---------------------------------------------------------------------------
// Kernel B: stage 4 -> g_w[b][cog][ci][tap][co16]
// grid: (co=64, b=16), 256 threads
// ---------------------------------------------------------------------------
__global__ void wgen_kernel(const float* __restrict__ w3,
                            const float* __restrict__ b3) {
    int co = blockIdx.x;
    int b  = blockIdx.y;
    __shared__ float k3s[288];        // [c(32)][t(9)]
    __shared__ float w3s[64 * 32];    // rows co*64 .. co*64+63
    int tid = threadIdx.x;

    for (int i = tid; i < 288; i += 256) k3s[i] = g_k3[b * 288 + i];
    for (int i = tid; i < 2048; i += 256) w3s[i] = w3[(co * 64) * 32 + i];
    __syncthreads();

    int cog = co >> 4, col = co & 15;
    for (int e = tid; e < 576; e += 256) {
        int ci = e / 9, t = e % 9;
        float s = b3[co * 64 + ci];
#pragma unroll
        for (int c = 0; c < 32; c++) s += w3s[ci * 32 + c] * k3s[c * 9 + t];
        g_w[((((b * 4 + cog) * 64 + ci) * 9 + t) << 4) + col] = s;
    }
}

// ---------------------------------------------------------------------------
// Kernel C: conv. grid (16 tiles, 4 cog, 16 b), 256 threads, 2 CTAs/SM.
// Thread = 4 horizontal pixels x 16 co; co-pairs packed in f32x2 halves.
// ci streamed through smem in chunks of 16.
// ---------------------------------------------------------------------------
__global__ void __launch_bounds__(256, 2)
conv_kernel(const float* __restrict__ x, const float* __restrict__ bias,
            float* __restrict__ y) {
    int tile = blockIdx.x;            // 0..15 : 4 across x, 4 down y
    int cog  = blockIdx.y;            // 0..3
    int b    = blockIdx.z;            // 0..15
    int tx0 = (tile & 3) * TW;
    int ty0 = (tile >> 2) * TH;

    extern __shared__ float smem[];
    float* xs = smem;                  // [CHUNK][34][XPITCH]
    float* ws = smem + XS_CH;          // [CHUNK][9][16]

    const float* xb = x + ((size_t)b * CIN) * (Hdim * Wdim);
    const float* wg = g_w + (size_t)((b * 4 + cog) * 64) * 144;
    int tid = threadIdx.x;

    int p   = tid & 7;    // pixel quad index: px = 4p..4p+3
    int row = tid >> 3;   // 0..31

    unsigned long long acc[8][4];
#pragma unroll
    for (int i = 0; i < 8; i++)
#pragma unroll
        for (int j = 0; j < 4; j++) acc[i][j] = 0ULL;

    for (int ch = 0; ch < CIN / CHUNK; ch++) {
        // ---- load x chunk (with zero halo) ----
        for (int i = tid; i < CHUNK * 34 * 34; i += 256) {
            int ci = i / (34 * 34);
            int rr = (i / 34) % 34;
            int cc = i % 34;
            int gy = ty0 - 1 + rr;
            int gx = tx0 - 1 + cc;
            float v = 0.f;
            if ((unsigned)gy < (unsigned)Hdim && (unsigned)gx < (unsigned)Wdim)
                v = xb[(ch * CHUNK + ci) * (Hdim * Wdim) + gy * Wdim + gx];
            xs[ci * (34 * XPITCH) + rr * XPITCH + cc] = v;
        }
        // ---- load weight chunk ----
        for (int i = tid; i < WS_CH; i += 256) ws[i] = wg[ch * WS_CH + i];
        __syncthreads();

        for (int ci = 0; ci < CHUNK; ci++) {
            const float* xp = xs + ci * (34 * XPITCH) + row * XPITCH + 4 * p;
            float xv[3][6];
#pragma unroll
            for (int r3 = 0; r3 < 3; r3++)
#pragma unroll
                for (int c6 = 0; c6 < 6; c6++) xv[r3][c6] = xp[r3 * XPITCH + c6];

            const float* wp = ws + ci * 144;
#pragma unroll
            for (int kr = 0; kr < 3; kr++) {
                unsigned long long xd[6];
#pragma unroll
                for (int c6 = 0; c6 < 6; c6++) xd[c6] = pack2(xv[kr][c6], xv[kr][c6]);
#pragma unroll
                for (int kc = 0; kc < 3; kc++) {
                    const ulonglong2* wq =
                        reinterpret_cast<const ulonglong2*>(wp + (kr * 3 + kc) * 16);
#pragma unroll
                    for (int q = 0; q < 4; q++) {
                        ulonglong2 wv = wq[q];           // co (4q,4q+1),(4q+2,4q+3)
#pragma unroll
                        for (int j = 0; j < 4; j++) {
                            fma2(acc[2 * q + 0][j], xd[kc + j], wv.x);
                            fma2(acc[2 * q + 1][j], xd[kc + j], wv.y);
                        }
                    }
                }
            }
        }
        __syncthreads();
    }

    // ---- epilogue: add bias, one STG.128 (4 px) per co ----
    int gx = tx0 + 4 * p;
    int gy = ty0 + row;
    float* yb = y + ((size_t)b * COUT + cog * 16) * (Hdim * Wdim) + gy * Wdim + gx;
#pragma unroll
    for (int pr = 0; pr < 8; pr++) {
        float bi0 = bias[cog * 16 + 2 * pr];
        float bi1 = bias[cog * 16 + 2 * pr + 1];
        float lo[4], hi[4];
#pragma unroll
        for (int j = 0; j < 4; j++) unpack2(acc[pr][j], lo[j], hi[j]);
        float4 o0 = make_float4(lo[0] + bi0, lo[1] + bi0, lo[2] + bi0, lo[3] + bi0);
        float4 o1 = make_float4(hi[0] + bi1, hi[1] + bi1, hi[2] + bi1, hi[3] + bi1);
        *reinterpret_cast<float4*>(yb + (size_t)(2 * pr) * (Hdim * Wdim))     = o0;
        *reinterpret_cast<float4*>(yb + (size_t)(2 * pr + 1) * (Hdim * Wdim)) = o1;
    }
}

// ---------------------------------------------------------------------------
extern "C" void kernel_launch(void* const* d_in, const int* in_sizes, int n_in,
                              void* d_out, int out_size) {
    const float* x    = (const float*)d_in[0];
    const float* h    = (const float*)d_in[1];
    const float* fc_w = (const float*)d_in[2];
    const float* fc_b = (const float*)d_in[3];
    const float* w1   = (const float*)d_in[4];
    const float* b1   = (const float*)d_in[5];
    const float* w2   = (const float*)d_in[6];
    const float* b2   = (const float*)d_in[7];
    const float* w3   = (const float*)d_in[8];
    const float* b3   = (const float*)d_in[9];
    const float* bias = (const float*)d_in[10];
    float* y = (float*)d_out;

    cudaFuncSetAttribute(conv_kernel, cudaFuncAttributeMaxDynamicSharedMemorySize,
                         SMEM_BYTES);

    knet_kernel<<<16, 288>>>(h, fc_w, fc_b, w1, b1, w2, b2);
    wgen_kernel<<<dim3(64, 16), 256>>>(w3, b3);
    conv_kernel<<<dim3(16, 4, 16), 256, SMEM_BYTES>>>(x, bias, y);
}

// round 5
// speedup vs baseline: 2.1904x; 2.1904x over previous
#include <cuda_runtime.h>
#include <cuda_bf16.h>
#include <cstdint>

#define Bn 16

// A staging: [ver2][slot4][px row 0..129][ci 64, pitch 72 elems = 144B]
#define APITCH 144
#define ASLOT  (130 * APITCH)          // 18720
#define AVER   (4 * ASLOT)             // 74880
#define BS_OFF (2 * AVER)              // 149760
#define BVER   9216                    // 64 ci x 144B
#define BBUF   (2 * BVER)              // 18432 (hi+lo, one tap)
#define BIAS_OFF (BS_OFF + 2 * BBUF)   // 186624
#define SMEM_TOTAL (BIAS_OFF + 256)    // 186880

// weights: per (b,tap): [ver2][ci64][co pitch 72] bf16 = 9216 elems
__device__ __nv_bfloat16 g_w[Bn * 9 * 9216];

__device__ __forceinline__ float lrelu(float v) { return v > 0.f ? v : 0.01f * v; }

__device__ __forceinline__ uint32_t smem_u32(const void* p) {
    uint32_t a;
    asm("{ .reg .u64 t; cvta.to.shared.u64 t, %1; cvt.u32.u64 %0, t; }" : "=r"(a) : "l"(p));
    return a;
}
__device__ __forceinline__ void ldsm4(uint32_t* r, uint32_t a) {
    asm volatile("ldmatrix.sync.aligned.m8n8.x4.shared.b16 {%0,%1,%2,%3},[%4];"
        : "=r"(r[0]), "=r"(r[1]), "=r"(r[2]), "=r"(r[3]) : "r"(a));
}
__device__ __forceinline__ void ldsm4t(uint32_t* r, uint32_t a) {
    asm volatile("ldmatrix.sync.aligned.m8n8.x4.trans.shared.b16 {%0,%1,%2,%3},[%4];"
        : "=r"(r[0]), "=r"(r[1]), "=r"(r[2]), "=r"(r[3]) : "r"(a));
}
__device__ __forceinline__ void mma16(float* c, const uint32_t* a, uint32_t b0, uint32_t b1) {
    asm volatile("mma.sync.aligned.m16n8k16.row.col.f32.bf16.bf16.f32 "
        "{%0,%1,%2,%3},{%4,%5,%6,%7},{%8,%9},{%0,%1,%2,%3};"
        : "+f"(c[0]), "+f"(c[1]), "+f"(c[2]), "+f"(c[3])
        : "r"(a[0]), "r"(a[1]), "r"(a[2]), "r"(a[3]), "r"(b0), "r"(b1));
}
__device__ __forceinline__ void cpa16(uint32_t dst, const void* src) {
    asm volatile("cp.async.cg.shared.global [%0],[%1],16;" :: "r"(dst), "l"(src));
}
#define CP_COMMIT() asm volatile("cp.async.commit_group;" ::: "memory")
#define CP_WAIT0()  asm volatile("cp.async.wait_group 0;" ::: "memory")

// ---------------------------------------------------------------------------
// wgen: full hypernet -> g_w (bf16 hi/lo). grid (64 co, 16 b), 256 thr.
// ---------------------------------------------------------------------------
__global__ void wgen_kernel(const float* __restrict__ h,
                            const float* __restrict__ fc_w, const float* __restrict__ fc_b,
                            const float* __restrict__ w1, const float* __restrict__ b1,
                            const float* __restrict__ w2, const float* __restrict__ b2,
                            const float* __restrict__ w3, const float* __restrict__ b3) {
    int co = blockIdx.x, b = blockIdx.y, tid = threadIdx.x;
    __shared__ float k1[144], k2[288], k3[288], w3s[64 * 32];

    if (tid < 144) {
        float s = fc_b[tid];
#pragma unroll
        for (int q = 0; q < 8; q++) s += h[b * 8 + q] * fc_w[tid * 8 + q];
        k1[tid] = lrelu(s);
    }
    __syncthreads();
    for (int i = tid; i < 288; i += 256) {
        int o = i / 9, t = i % 9;
        float s = b1[o];
#pragma unroll
        for (int c = 0; c < 16; c++) s += w1[o * 16 + c] * k1[c * 9 + t];
        k2[i] = lrelu(s);
    }
    __syncthreads();
    for (int i = tid; i < 288; i += 256) {
        int o = i / 9, t = i % 9;
        float s = b2[o];
#pragma unroll
        for (int c = 0; c < 32; c++) s += w2[o * 32 + c] * k2[c * 9 + t];
        k3[i] = lrelu(s);
    }
    for (int i = tid; i < 2048; i += 256) w3s[i] = w3[(co * 64) * 32 + i];
    __syncthreads();

    for (int e = tid; e < 576; e += 256) {
        int ci = e / 9, t = e % 9;
        float s = b3[co * 64 + ci];
#pragma unroll
        for (int c = 0; c < 32; c++) s += w3s[ci * 32 + c] * k3[c * 9 + t];
        __nv_bfloat16 hi = __float2bfloat16(s);
        __nv_bfloat16 lo = __float2bfloat16(s - __bfloat162float(hi));
        size_t base = (size_t)(b * 9 + t) * 9216 + (size_t)ci * 72 + co;
        g_w[base] = hi;
        g_w[base + 4608] = lo;
    }
}

// ---------------------------------------------------------------------------
// conv: implicit GEMM via mma.sync bf16. grid (64 row-pairs, 16 b), 256 thr.
// ---------------------------------------------------------------------------
__global__ void __launch_bounds__(256, 1)
conv_kernel(const float* __restrict__ x, const float* __restrict__ bias,
            float* __restrict__ y) {
    extern __shared__ char smem[];
    uint32_t xs_sh = smem_u32(smem);
    uint32_t bs_sh = xs_sh + BS_OFF;
    int tid = threadIdx.x, lane = tid & 31, wid = tid >> 5;
    int y0 = blockIdx.x * 2, b = blockIdx.y;

    // prologue: start B tap0 load
    {
        const char* g0 = (const char*)(g_w + (size_t)(b * 9) * 9216);
        for (int i = tid; i < 1152; i += 256) cpa16(bs_sh + i * 16, g0 + i * 16);
        CP_COMMIT();
    }
    if (tid < 64) ((float*)(smem + BIAS_OFF))[tid] = bias[tid];

    // zero halo rows (px -1 and px 128) for all (ver, slot)
    uint4 z4 = make_uint4(0, 0, 0, 0);
    if (tid < 144) {
        int v = tid / 72, rem = tid % 72;
        int sl = rem / 18, rr = (rem / 9) & 1, ck = rem % 9;
        *(uint4*)(smem + v * AVER + sl * ASLOT + (rr ? 129 * APITCH : 0) + ck * 16) = z4;
    }
    // zero invalid slots (edge row-pairs)
    if (y0 == 0)
        for (int i = tid; i < 2340; i += 256)
            *(uint4*)(smem + (i / 1170) * AVER + (i % 1170) * 16) = z4;
    if (y0 == 126)
        for (int i = tid; i < 2340; i += 256)
            *(uint4*)(smem + (i / 1170) * AVER + 3 * ASLOT + (i % 1170) * 16) = z4;

    // stage A: 4 input rows (y0-1..y0+2), bf16 hi/lo, [px][ci] pitch 144B
    for (int i = tid; i < 4096; i += 256) {
        int px = i & 127, oct = (i >> 7) & 7, sl = i >> 10;
        int yy = y0 - 1 + sl;
        if ((unsigned)yy > 127u) continue;
        const float* gp = x + (((size_t)(b * 64 + oct * 8)) * 128 + yy) * 128 + px;
        uint32_t hh[4], ll[4];
#pragma unroll
        for (int c = 0; c < 4; c++) {
            float f0 = __ldg(gp + (size_t)(2 * c) * 16384);
            float f1 = __ldg(gp + (size_t)(2 * c + 1) * 16384);
            __nv_bfloat16 h0 = __float2bfloat16(f0), h1 = __float2bfloat16(f1);
            __nv_bfloat16 l0 = __float2bfloat16(f0 - __bfloat162float(h0));
            __nv_bfloat16 l1 = __float2bfloat16(f1 - __bfloat162float(h1));
            hh[c] = (uint32_t)__bfloat16_as_ushort(h0) | ((uint32_t)__bfloat16_as_ushort(h1) << 16);
            ll[c] = (uint32_t)__bfloat16_as_ushort(l0) | ((uint32_t)__bfloat16_as_ushort(l1) << 16);
        }
        uint32_t off = sl * ASLOT + (px + 1) * APITCH + oct * 16;
        *(uint4*)(smem + off) = make_uint4(hh[0], hh[1], hh[2], hh[3]);
        *(uint4*)(smem + AVER + off) = make_uint4(ll[0], ll[1], ll[2], ll[3]);
    }
    CP_WAIT0();
    __syncthreads();

    int r = wid >> 2;                 // output row within pair
    int wpx = (wid & 3) * 32;         // warp's px base
    uint32_t lane_off = (uint32_t)((((lane >> 3) & 1) * 8 + (lane & 7)) * 144 + (lane >> 4) * 16);

    float acc[64];
#pragma unroll
    for (int i = 0; i < 64; i++) acc[i] = 0.f;

    for (int t = 0; t < 9; t++) {
        int buf = t & 1;
        if (t < 8) {
            const char* gt = (const char*)(g_w + (size_t)(b * 9 + t + 1) * 9216);
            uint32_t db = bs_sh + (buf ^ 1) * BBUF;
            for (int i = tid; i < 1152; i += 256) cpa16(db + i * 16, gt + i * 16);
            CP_COMMIT();
        }
        int dy = t / 3 - 1, dx = t % 3 - 1;
        int slot = 1 + dy + r;
        uint32_t abase = xs_sh + slot * ASLOT + (uint32_t)(wpx + 1 + dx) * APITCH + lane_off;
        uint32_t bbase = bs_sh + buf * BBUF + lane_off;
#pragma unroll
        for (int kc = 0; kc < 4; kc++) {
            uint32_t ah[2][4], al[2][4];
            ldsm4(ah[0], abase + kc * 32);
            ldsm4(ah[1], abase + kc * 32 + 2304);
            ldsm4(al[0], abase + AVER + kc * 32);
            ldsm4(al[1], abase + AVER + kc * 32 + 2304);
#pragma unroll
            for (int np = 0; np < 4; np++) {
                uint32_t bh[4], bl[4];
                ldsm4t(bh, bbase + kc * 2304 + np * 32);
                ldsm4t(bl, bbase + kc * 2304 + np * 32 + BVER);
#pragma unroll
                for (int mt = 0; mt < 2; mt++) {
                    float* A0 = acc + ((mt * 4 + np) * 2 + 0) * 4;
                    float* A1 = acc + ((mt * 4 + np) * 2 + 1) * 4;
                    mma16(A0, ah[mt], bh[0], bh[1]);
                    mma16(A1, ah[mt], bh[2], bh[3]);
                    mma16(A0, al[mt], bh[0], bh[1]);
                    mma16(A1, al[mt], bh[2], bh[3]);
                    mma16(A0, ah[mt], bl[0], bl[1]);
                    mma16(A1, ah[mt], bl[2], bl[3]);
                }
            }
        }
        if (t < 8) { CP_WAIT0(); __syncthreads(); }
    }

    // epilogue: regs -> smem transpose [co][px pitch132] -> coalesced STG
    __syncthreads();
    {
        float* dsm = (float*)(smem + (r ? 33792 : 0));
        int g = lane >> 2, tq = lane & 3;
#pragma unroll
        for (int mt = 0; mt < 2; mt++)
#pragma unroll
            for (int np = 0; np < 4; np++)
#pragma unroll
                for (int s = 0; s < 2; s++) {
                    float* a4 = acc + ((mt * 4 + np) * 2 + s) * 4;
                    int co = np * 16 + s * 8 + 2 * tq;
                    int px = wpx + mt * 16 + g;
                    dsm[co * 132 + px] = a4[0];
                    dsm[(co + 1) * 132 + px] = a4[1];
                    dsm[co * 132 + px + 8] = a4[2];
                    dsm[(co + 1) * 132 + px + 8] = a4[3];
                }
    }
    __syncthreads();
    for (int i = tid; i < 4096; i += 256) {
        int rr = i >> 11, co = (i >> 5) & 63, q = i & 31;
        float4 v = *(float4*)((float*)(smem + (rr ? 33792 : 0)) + co * 132 + q * 4);
        float bb = ((float*)(smem + BIAS_OFF))[co];
        v.x += bb; v.y += bb; v.z += bb; v.w += bb;
        *(float4*)(y + (((size_t)(b * 64 + co)) * 128 + y0 + rr) * 128 + q * 4) = v;
    }
}

// ---------------------------------------------------------------------------
extern "C" void kernel_launch(void* const* d_in, const int* in_sizes, int n_in,
                              void* d_out, int out_size) {
    const float* x    = (const float*)d_in[0];
    const float* h    = (const float*)d_in[1];
    const float* fc_w = (const float*)d_in[2];
    const float* fc_b = (const float*)d_in[3];
    const float* w1   = (const float*)d_in[4];
    const float* b1   = (const float*)d_in[5];
    const float* w2   = (const float*)d_in[6];
    const float* b2   = (const float*)d_in[7];
    const float* w3   = (const float*)d_in[8];
    const float* b3   = (const float*)d_in[9];
    const float* bias = (const float*)d_in[10];
    float* y = (float*)d_out;

    cudaFuncSetAttribute(conv_kernel, cudaFuncAttributeMaxDynamicSharedMemorySize,
                         SMEM_TOTAL);

    wgen_kernel<<<dim3(64, 16), 256>>>(h, fc_w, fc_b, w1, b1, w2, b2, w3, b3);
    conv_kernel<<<dim3(64, 16), 256, SMEM_TOTAL>>>(x, bias, y);
}